// round 9
// baseline (speedup 1.0000x reference)
#include <cuda_runtime.h>
#include <stdint.h>

#define TT 64          // num types
#define CC 128         // channels
#define TC (TT * CC)   // 8192 stat entries
#define MAXN (1 << 21) // max rows (N = 1e6 fits)
#define GH 444         // grid for hist/scatter/gather

// ---- device scratch (no allocations allowed) ----
__device__ int   g_perm[MAXN];        // rows sorted by type (8 MB)
__device__ int   g_typecnt[TT];
__device__ int   g_blockoff[GH * TT]; // per-block within-type offsets
__device__ int   g_typestart[TT + 1];
__device__ float g_sum[TC];
__device__ float g_sum2[TC];
__device__ float g_cnt[TT];
__device__ float g_mean[TC];
__device__ float g_rstd[TC];
__device__ int   g_is64;

// ---------------------------------------------------------------------------
// Kernel 0: zero accumulators + detect int64-vs-int32 type_vec encoding.
// int64 values 0..63 little-endian -> every odd int32 word == 0.
// ---------------------------------------------------------------------------
__global__ void k_init(const void* __restrict__ tv, long long n) {
    int idx = blockIdx.x * blockDim.x + threadIdx.x;
    if (idx < TC) { g_sum[idx] = 0.f; g_sum2[idx] = 0.f; }
    if (idx < TT) g_typecnt[idx] = 0;
    if (idx == 0) {
        const int* p = (const int*)tv;
        int lim = (n >= 256) ? 256 : (int)n;
        int is64 = 1;
        for (int i = 1; i < lim; i += 2)
            if (p[i] != 0) { is64 = 0; break; }
        g_is64 = is64;
    }
}

// ---------------------------------------------------------------------------
// Kernel 1: per-block histogram with WARP-AGGREGATED atomics
// (__match_any_sync groups same-type lanes; leader adds popc once).
// ---------------------------------------------------------------------------
__global__ void __launch_bounds__(256) k_hist(
    const void* __restrict__ tv, long long N)
{
    __shared__ int hist[TT];
    const int tid  = threadIdx.x;
    const int lane = tid & 31;
    const int w    = tid >> 5;
    if (tid < TT) hist[tid] = 0;
    __syncthreads();

    const int is64 = g_is64;
    const long long* __restrict__ tv64 = (const long long*)tv;
    const int*       __restrict__ tv32 = (const int*)tv;

    const long long chunk = (N + GH - 1) / GH;
    const long long lo = (long long)blockIdx.x * chunk;
    const long long hi = (lo + chunk < N) ? lo + chunk : N;

    // warp-uniform iteration: all lanes of a warp execute the same trips
    for (long long ib = lo + (w << 5); ib < hi; ib += 256) {
        long long i = ib + lane;
        bool valid = (i < hi);
        int t = valid ? (is64 ? (int)tv64[i] : tv32[i]) : (TT + lane);
        unsigned mask = __match_any_sync(0xffffffffu, t);
        if (valid && lane == (__ffs(mask) - 1))
            atomicAdd(&hist[t], __popc(mask));
    }
    __syncthreads();
    if (tid < TT)
        g_blockoff[blockIdx.x * TT + tid] = atomicAdd(&g_typecnt[tid], hist[tid]);
}

// ---------------------------------------------------------------------------
// Kernel 2: exclusive prefix over 64 type counts (+ float counts for k_fin).
// ---------------------------------------------------------------------------
__global__ void k_prefix() {
    if (threadIdx.x == 0) {
        int acc = 0;
        for (int t = 0; t < TT; t++) {
            g_typestart[t] = acc;
            acc += g_typecnt[t];
            g_cnt[t] = (float)g_typecnt[t];
        }
        g_typestart[TT] = acc;
    }
}

// ---------------------------------------------------------------------------
// Kernel 3: scatter row indices into type-sorted order. Warp-aggregated
// rank assignment: one smem atomic per (warp, distinct type) instead of
// per row; within-group rank = popc of lower matching lanes.
// ---------------------------------------------------------------------------
__global__ void __launch_bounds__(256) k_scatter(
    const void* __restrict__ tv, long long N)
{
    __shared__ int srank[TT];
    __shared__ int sbase[TT];
    const int tid  = threadIdx.x;
    const int lane = tid & 31;
    const int w    = tid >> 5;
    if (tid < TT) {
        srank[tid] = 0;
        sbase[tid] = g_typestart[tid] + g_blockoff[blockIdx.x * TT + tid];
    }
    __syncthreads();

    const int is64 = g_is64;
    const long long* __restrict__ tv64 = (const long long*)tv;
    const int*       __restrict__ tv32 = (const int*)tv;

    const long long chunk = (N + GH - 1) / GH;
    const long long lo = (long long)blockIdx.x * chunk;
    const long long hi = (lo + chunk < N) ? lo + chunk : N;

    for (long long ib = lo + (w << 5); ib < hi; ib += 256) {
        long long i = ib + lane;
        bool valid = (i < hi);
        int t = valid ? (is64 ? (int)tv64[i] : tv32[i]) : (TT + lane);
        unsigned mask = __match_any_sync(0xffffffffu, t);
        if (valid) {
            int leader = __ffs(mask) - 1;
            int lrank  = __popc(mask & ((1u << lane) - 1));
            int base = 0;
            if (lane == leader) base = atomicAdd(&srank[t], __popc(mask));
            base = __shfl_sync(mask, base, leader);
            g_perm[sbase[t] + base + lrank] = (int)i;
        }
    }
}

// ---------------------------------------------------------------------------
// Kernel 4: gather-accumulate. Warp-per-row over perm (type-sorted), lane l
// owns channels [4l,4l+4). REGISTER float4 sum/sumsq — no smem RMW chain.
// Type derived from perm position; flush via atomicAdd only at type
// boundaries / range end (~2 flushes per warp).
// ---------------------------------------------------------------------------
#define CW 8
__global__ void __launch_bounds__(256) k_gather(
    const float* __restrict__ x, long long N)
{
    __shared__ int st[TT + 1];
    const int tid  = threadIdx.x;
    const int lane = tid & 31;
    for (int i = tid; i < TT + 1; i += 256) st[i] = g_typestart[i];
    __syncthreads();

    const long long nwarps = (long long)GH * 8;
    const long long gw  = (long long)blockIdx.x * 8 + (tid >> 5);
    const long long per = (N + nwarps - 1) / nwarps;
    const long long a = gw * per;
    const long long b = (a + per < N) ? a + per : N;
    if (a >= b) return;

    int t = 0;
    while (st[t + 1] <= (int)a) t++;
    int nxt = st[t + 1];

    float4 s = make_float4(0.f, 0.f, 0.f, 0.f);
    float4 q = make_float4(0.f, 0.f, 0.f, 0.f);
    const float4* __restrict__ x4 = (const float4*)x;

#define FLUSH() do {                                                      \
        if (q.x + q.y + q.z + q.w != 0.f) {                               \
            int base_ = t * CC + 4 * lane;                                \
            atomicAdd(&g_sum[base_ + 0], s.x);                            \
            atomicAdd(&g_sum[base_ + 1], s.y);                            \
            atomicAdd(&g_sum[base_ + 2], s.z);                            \
            atomicAdd(&g_sum[base_ + 3], s.w);                            \
            atomicAdd(&g_sum2[base_ + 0], q.x);                           \
            atomicAdd(&g_sum2[base_ + 1], q.y);                           \
            atomicAdd(&g_sum2[base_ + 2], q.z);                           \
            atomicAdd(&g_sum2[base_ + 3], q.w);                           \
            s = make_float4(0.f, 0.f, 0.f, 0.f);                          \
            q = make_float4(0.f, 0.f, 0.f, 0.f);                          \
        }                                                                  \
    } while (0)

    int rrA[CW];
    #pragma unroll
    for (int u = 0; u < CW; u++)
        rrA[u] = (a + u < b) ? g_perm[a + u] : 0;

    for (long long i = a; i < b; i += CW) {
        int rrB[CW];
        const long long i2 = i + CW;
        #pragma unroll
        for (int u = 0; u < CW; u++)
            rrB[u] = (i2 + u < b) ? g_perm[i2 + u] : 0;

        const int m = (int)((b - i < CW) ? (b - i) : CW);
        float4 xv[CW];
        #pragma unroll
        for (int u = 0; u < CW; u++)
            if (u < m) xv[u] = x4[(long long)rrA[u] * (CC / 4) + lane];

        #pragma unroll
        for (int u = 0; u < CW; u++) {
            if (u < m) {
                const int idx = (int)(i + u);
                if (idx >= nxt) {            // type boundary (rare)
                    FLUSH();
                    do { t++; } while (st[t + 1] <= idx);
                    nxt = st[t + 1];
                }
                s.x += xv[u].x; s.y += xv[u].y;
                s.z += xv[u].z; s.w += xv[u].w;
                q.x = fmaf(xv[u].x, xv[u].x, q.x);
                q.y = fmaf(xv[u].y, xv[u].y, q.y);
                q.z = fmaf(xv[u].z, xv[u].z, q.z);
                q.w = fmaf(xv[u].w, xv[u].w, q.w);
            }
        }
        #pragma unroll
        for (int u = 0; u < CW; u++) rrA[u] = rrB[u];
    }
    FLUSH();
#undef FLUSH
}

// ---------------------------------------------------------------------------
// Kernel 5: finalize mean / rstd (cnt clamped >= 1, var clamped >= 0,
// std = sqrt(var + 1e-5)) — matches the reference exactly.
// ---------------------------------------------------------------------------
__global__ void k_fin() {
    int e = blockIdx.x * blockDim.x + threadIdx.x;
    if (e >= TC) return;
    float cnt  = fmaxf(g_cnt[e >> 7], 1.f);
    float mean = g_sum[e] / cnt;
    float var  = fmaxf(g_sum2[e] / cnt - mean * mean, 0.f);
    g_mean[e] = mean;
    g_rstd[e] = 1.f / sqrtf(var + 1e-5f);
}

// ---------------------------------------------------------------------------
// Kernel 6: normalize. Warp-per-row, float4 loads/stores, stats staged in
// shared (separate mean/rstd tables, conflict-free LDS.128).
// grid = 296: exactly 2 blocks/SM resident (regs=63, 512 thr) -> ONE wave,
// no straggler tail (was 444 = 1.5 waves).
// ---------------------------------------------------------------------------
#define NRM_U 4
#define NRM_GRID 296
__global__ void __launch_bounds__(512) k_norm(
    const float* __restrict__ x, const void* __restrict__ tv,
    float* __restrict__ out, long long N)
{
    extern __shared__ float smn[];
    float* smean = smn;        // TC
    float* srstd = smn + TC;   // TC
    const int tid = threadIdx.x;

    #pragma unroll
    for (int i = tid; i < TC; i += 512) {
        smean[i] = g_mean[i];
        srstd[i] = g_rstd[i];
    }
    __syncthreads();

    const int is64 = g_is64;
    const long long* __restrict__ tv64 = (const long long*)tv;
    const int*       __restrict__ tv32 = (const int*)tv;

    const int lane = tid & 31;
    const long long w  = (long long)blockIdx.x * 16 + (tid >> 5);
    const long long nw = (long long)NRM_GRID * 16;
    const float4* __restrict__ x4 = (const float4*)x;
    float4* __restrict__ o4 = (float4*)out;

    for (long long r0 = w * NRM_U; r0 < N; r0 += nw * NRM_U) {
        float4 xv[NRM_U];
        int    ty[NRM_U];

        #pragma unroll
        for (int u = 0; u < NRM_U; u++) {
            long long r = r0 + u;
            if (r < N) {
                ty[u] = is64 ? (int)tv64[r] : tv32[r];
                xv[u] = x4[r * (CC / 4) + lane];
            } else ty[u] = -1;
        }
        #pragma unroll
        for (int u = 0; u < NRM_U; u++) {
            if (ty[u] >= 0) {
                int o = ty[u] * CC + 4 * lane;
                float4 mn = *(const float4*)&smean[o];
                float4 rs = *(const float4*)&srstd[o];
                float4 res;
                res.x = (xv[u].x - mn.x) * rs.x;
                res.y = (xv[u].y - mn.y) * rs.y;
                res.z = (xv[u].z - mn.z) * rs.z;
                res.w = (xv[u].w - mn.w) * rs.w;
                o4[(r0 + u) * (CC / 4) + lane] = res;
            }
        }
    }
}

// ---------------------------------------------------------------------------
// Launch
// ---------------------------------------------------------------------------
extern "C" void kernel_launch(void* const* d_in, const int* in_sizes, int n_in,
                              void* d_out, int out_size)
{
    const float* x  = (const float*)d_in[0];
    const void*  tv = d_in[1];
    float* out = (float*)d_out;
    const long long N = (long long)in_sizes[1];   // rows (type_vec length)

    const int NRM_SMEM = 2 * TC * (int)sizeof(float); // 64 KB
    cudaFuncSetAttribute(k_norm, cudaFuncAttributeMaxDynamicSharedMemorySize, NRM_SMEM);

    k_init   <<<32, 256>>>(tv, N);
    k_hist   <<<GH, 256>>>(tv, N);
    k_prefix <<<1, 32>>>();
    k_scatter<<<GH, 256>>>(tv, N);
    k_gather <<<GH, 256>>>(x, N);
    k_fin    <<<32, 256>>>();
    k_norm   <<<NRM_GRID, 512, NRM_SMEM>>>(x, tv, out, N);
}

// round 10
// speedup vs baseline: 1.0654x; 1.0654x over previous
#include <cuda_runtime.h>
#include <stdint.h>

#define TT 64          // num types
#define CC 128         // channels
#define TC (TT * CC)   // 8192 stat entries
#define MAXN (1 << 21) // max rows (N = 1e6 fits)
#define GH 444         // grid for sort/gather (148 SMs x 3 — all co-resident)

// ---- device scratch (no allocations allowed) ----
__device__ int   g_perm[MAXN];        // rows sorted by type (8 MB)
__device__ int   g_typecnt[TT];
__device__ int   g_typestart[TT + 1];
__device__ float g_sum[TC];
__device__ float g_sum2[TC];
__device__ float g_cnt[TT];
__device__ float g_mean[TC];
__device__ float g_rstd[TC];
__device__ int   g_is64;
__device__ int   g_arrive;            // grid-barrier counter (reset by k_init)

// ---------------------------------------------------------------------------
// Kernel 0: zero accumulators/counters + detect int64-vs-int32 type_vec.
// int64 values 0..63 little-endian -> every odd int32 word == 0.
// ---------------------------------------------------------------------------
__global__ void k_init(const void* __restrict__ tv, long long n) {
    int idx = blockIdx.x * blockDim.x + threadIdx.x;
    if (idx < TC) { g_sum[idx] = 0.f; g_sum2[idx] = 0.f; }
    if (idx < TT) g_typecnt[idx] = 0;
    if (idx == 0) {
        g_arrive = 0;
        const int* p = (const int*)tv;
        int lim = (n >= 256) ? 256 : (int)n;
        int is64 = 1;
        for (int i = 1; i < lim; i += 2)
            if (p[i] != 0) { is64 = 0; break; }
        g_is64 = is64;
    }
}

// ---------------------------------------------------------------------------
// Kernel 1: FUSED hist + prefix + scatter (single pass over tv).
//   Phase A: cache this block's tv chunk in smem while histogramming;
//            publish per-type block offsets via global atomicAdd.
//   Grid barrier (all 444 blocks co-resident: 10KB smem, 3 blocks/SM).
//   Phase B: every block scans g_typecnt in smem (Hillis-Steele, 64 wide),
//            computes its scatter bases, scatters FROM THE SMEM CACHE.
//   Block 0 publishes g_typestart / g_cnt for the later kernels.
//   dyn smem: chunk*4 bytes (tv cache).
// ---------------------------------------------------------------------------
__global__ void __launch_bounds__(256) k_sort(
    const void* __restrict__ tv, long long N)
{
    extern __shared__ int stv[];          // chunk cache
    __shared__ int hist[TT];              // phase A hist -> phase B srank
    __shared__ int sbase[TT];
    __shared__ int sscan[TT];
    __shared__ int scnt0[TT];
    __shared__ int myoff[TT];

    const int tid = threadIdx.x;
    const long long chunk = (N + GH - 1) / GH;
    const long long lo = (long long)blockIdx.x * chunk;
    const long long hi = (lo + chunk < N) ? lo + chunk : N;
    const int cnt = (int)((hi > lo) ? (hi - lo) : 0);

    if (tid < TT) hist[tid] = 0;
    __syncthreads();

    const int is64 = g_is64;
    const long long* __restrict__ tv64 = (const long long*)tv;
    const int*       __restrict__ tv32 = (const int*)tv;

    // Phase A: load chunk -> smem cache + histogram (fire-and-forget atomics)
    for (int i = tid; i < cnt; i += 256) {
        int t = is64 ? (int)tv64[lo + i] : tv32[lo + i];
        stv[i] = t;
        atomicAdd(&hist[t], 1);
    }
    __syncthreads();
    if (tid < TT)
        myoff[tid] = atomicAdd(&g_typecnt[tid], hist[tid]);

    // ---- grid barrier ----
    __syncthreads();
    __threadfence();
    if (tid == 0) {
        atomicAdd(&g_arrive, 1);
        while (*((volatile int*)&g_arrive) < GH)
            __nanosleep(64);
        __threadfence();
    }
    __syncthreads();

    // Phase B: local 64-wide exclusive scan of the final g_typecnt
    if (tid < TT) {
        int c = g_typecnt[tid];
        scnt0[tid] = c;
        sscan[tid] = c;
    }
    __syncthreads();
    #pragma unroll
    for (int off = 1; off < TT; off <<= 1) {
        int v = 0;
        if (tid < TT && tid >= off) v = sscan[tid - off];
        __syncthreads();
        if (tid < TT) sscan[tid] += v;
        __syncthreads();
    }
    if (tid < TT) {
        int excl = sscan[tid] - scnt0[tid];
        sbase[tid] = excl + myoff[tid];
        hist[tid] = 0;                      // reuse as srank
        if (blockIdx.x == 0) {
            g_typestart[tid] = excl;
            g_cnt[tid] = (float)scnt0[tid];
            if (tid == TT - 1) g_typestart[TT] = sscan[tid];
        }
    }
    __syncthreads();

    // Scatter from the smem cache (no second global tv read).
    for (int i = tid; i < cnt; i += 256) {
        int t = stv[i];
        int r = atomicAdd(&hist[t], 1);
        g_perm[sbase[t] + r] = (int)(lo + i);
    }
}

// ---------------------------------------------------------------------------
// Kernel 2: gather-accumulate. Warp-per-row over perm (type-sorted), lane l
// owns channels [4l,4l+4). REGISTER float4 sum/sumsq — no smem RMW chain.
// Type derived from perm position; flush via atomicAdd only at type
// boundaries / range end (~2 flushes per warp).
// ---------------------------------------------------------------------------
#define CW 8
__global__ void __launch_bounds__(256) k_gather(
    const float* __restrict__ x, long long N)
{
    __shared__ int st[TT + 1];
    const int tid  = threadIdx.x;
    const int lane = tid & 31;
    for (int i = tid; i < TT + 1; i += 256) st[i] = g_typestart[i];
    __syncthreads();

    const long long nwarps = (long long)GH * 8;
    const long long gw  = (long long)blockIdx.x * 8 + (tid >> 5);
    const long long per = (N + nwarps - 1) / nwarps;
    const long long a = gw * per;
    const long long b = (a + per < N) ? a + per : N;
    if (a >= b) return;

    int t = 0;
    while (st[t + 1] <= (int)a) t++;
    int nxt = st[t + 1];

    float4 s = make_float4(0.f, 0.f, 0.f, 0.f);
    float4 q = make_float4(0.f, 0.f, 0.f, 0.f);
    const float4* __restrict__ x4 = (const float4*)x;

#define FLUSH() do {                                                      \
        if (q.x + q.y + q.z + q.w != 0.f) {                               \
            int base_ = t * CC + 4 * lane;                                \
            atomicAdd(&g_sum[base_ + 0], s.x);                            \
            atomicAdd(&g_sum[base_ + 1], s.y);                            \
            atomicAdd(&g_sum[base_ + 2], s.z);                            \
            atomicAdd(&g_sum[base_ + 3], s.w);                            \
            atomicAdd(&g_sum2[base_ + 0], q.x);                           \
            atomicAdd(&g_sum2[base_ + 1], q.y);                           \
            atomicAdd(&g_sum2[base_ + 2], q.z);                           \
            atomicAdd(&g_sum2[base_ + 3], q.w);                           \
            s = make_float4(0.f, 0.f, 0.f, 0.f);                          \
            q = make_float4(0.f, 0.f, 0.f, 0.f);                          \
        }                                                                  \
    } while (0)

    int rrA[CW];
    #pragma unroll
    for (int u = 0; u < CW; u++)
        rrA[u] = (a + u < b) ? g_perm[a + u] : 0;

    for (long long i = a; i < b; i += CW) {
        int rrB[CW];
        const long long i2 = i + CW;
        #pragma unroll
        for (int u = 0; u < CW; u++)
            rrB[u] = (i2 + u < b) ? g_perm[i2 + u] : 0;

        const int m = (int)((b - i < CW) ? (b - i) : CW);
        float4 xv[CW];
        #pragma unroll
        for (int u = 0; u < CW; u++)
            if (u < m) xv[u] = x4[(long long)rrA[u] * (CC / 4) + lane];

        #pragma unroll
        for (int u = 0; u < CW; u++) {
            if (u < m) {
                const int idx = (int)(i + u);
                if (idx >= nxt) {            // type boundary (rare)
                    FLUSH();
                    do { t++; } while (st[t + 1] <= idx);
                    nxt = st[t + 1];
                }
                s.x += xv[u].x; s.y += xv[u].y;
                s.z += xv[u].z; s.w += xv[u].w;
                q.x = fmaf(xv[u].x, xv[u].x, q.x);
                q.y = fmaf(xv[u].y, xv[u].y, q.y);
                q.z = fmaf(xv[u].z, xv[u].z, q.z);
                q.w = fmaf(xv[u].w, xv[u].w, q.w);
            }
        }
        #pragma unroll
        for (int u = 0; u < CW; u++) rrA[u] = rrB[u];
    }
    FLUSH();
#undef FLUSH
}

// ---------------------------------------------------------------------------
// Kernel 3: finalize mean / rstd (cnt clamped >= 1, var clamped >= 0,
// std = sqrt(var + 1e-5)) — matches the reference exactly.
// ---------------------------------------------------------------------------
__global__ void k_fin() {
    int e = blockIdx.x * blockDim.x + threadIdx.x;
    if (e >= TC) return;
    float cnt  = fmaxf(g_cnt[e >> 7], 1.f);
    float mean = g_sum[e] / cnt;
    float var  = fmaxf(g_sum2[e] / cnt - mean * mean, 0.f);
    g_mean[e] = mean;
    g_rstd[e] = 1.f / sqrtf(var + 1e-5f);
}

// ---------------------------------------------------------------------------
// Kernel 4: normalize (at the HBM cap ~6.3 TB/s; proven round-8 design).
// Warp-per-row, float4 loads/stores, stats staged in shared as SEPARATE
// mean/rstd tables (conflict-free LDS.128). blockDim = 512, grid = 444.
// ---------------------------------------------------------------------------
#define NRM_U 4
__global__ void __launch_bounds__(512) k_norm(
    const float* __restrict__ x, const void* __restrict__ tv,
    float* __restrict__ out, long long N)
{
    extern __shared__ float smn[];
    float* smean = smn;        // TC
    float* srstd = smn + TC;   // TC
    const int tid = threadIdx.x;

    #pragma unroll
    for (int i = tid; i < TC; i += 512) {
        smean[i] = g_mean[i];
        srstd[i] = g_rstd[i];
    }
    __syncthreads();

    const int is64 = g_is64;
    const long long* __restrict__ tv64 = (const long long*)tv;
    const int*       __restrict__ tv32 = (const int*)tv;

    const int lane = tid & 31;
    const long long w  = (long long)blockIdx.x * 16 + (tid >> 5);
    const long long nw = (long long)gridDim.x * 16;
    const float4* __restrict__ x4 = (const float4*)x;
    float4* __restrict__ o4 = (float4*)out;

    for (long long r0 = w * NRM_U; r0 < N; r0 += nw * NRM_U) {
        float4 xv[NRM_U];
        int    ty[NRM_U];

        #pragma unroll
        for (int u = 0; u < NRM_U; u++) {
            long long r = r0 + u;
            if (r < N) {
                ty[u] = is64 ? (int)tv64[r] : tv32[r];
                xv[u] = x4[r * (CC / 4) + lane];
            } else ty[u] = -1;
        }
        #pragma unroll
        for (int u = 0; u < NRM_U; u++) {
            if (ty[u] >= 0) {
                int o = ty[u] * CC + 4 * lane;
                float4 mn = *(const float4*)&smean[o];
                float4 rs = *(const float4*)&srstd[o];
                float4 res;
                res.x = (xv[u].x - mn.x) * rs.x;
                res.y = (xv[u].y - mn.y) * rs.y;
                res.z = (xv[u].z - mn.z) * rs.z;
                res.w = (xv[u].w - mn.w) * rs.w;
                o4[(r0 + u) * (CC / 4) + lane] = res;
            }
        }
    }
}

// ---------------------------------------------------------------------------
// Launch
// ---------------------------------------------------------------------------
extern "C" void kernel_launch(void* const* d_in, const int* in_sizes, int n_in,
                              void* d_out, int out_size)
{
    const float* x  = (const float*)d_in[0];
    const void*  tv = d_in[1];
    float* out = (float*)d_out;
    const long long N = (long long)in_sizes[1];   // rows (type_vec length)

    const long long chunk = (N + GH - 1) / GH;
    const int SORT_SMEM = (int)(chunk * sizeof(int));   // tv cache (~9 KB @ N=1e6)
    const int NRM_SMEM  = 2 * TC * (int)sizeof(float);  // 64 KB

    cudaFuncSetAttribute(k_sort, cudaFuncAttributeMaxDynamicSharedMemorySize, SORT_SMEM);
    cudaFuncSetAttribute(k_norm, cudaFuncAttributeMaxDynamicSharedMemorySize, NRM_SMEM);

    k_init  <<<32, 256>>>(tv, N);
    k_sort  <<<GH, 256, SORT_SMEM>>>(tv, N);
    k_gather<<<GH, 256>>>(x, N);
    k_fin   <<<32, 256>>>();
    k_norm  <<<444, 512, NRM_SMEM>>>(x, tv, out, N);
}